// round 7
// baseline (speedup 1.0000x reference)
#include <cuda_runtime.h>
#include <math.h>

#define BATCH 8192
#define DIM 16
#define DIM1 48
#define VOCAB 32000
#define TTH 20
#define FULLM 0xffffffffu

// Intermediate o = [BATCH, 16] between the two kernels (static scratch, no allocs).
__device__ float g_o[BATCH * DIM];

// ---------------------------------------------------------------------------
// Kernel A: cooperative 16-lanes-per-row MLP pipeline (unchanged from R6 WIN).
// ---------------------------------------------------------------------------

#define S_M1 84   // 80 -> 84
#define S_M2 116  // 112 -> 116
#define S_M3 52   // 48 -> 52

__device__ __forceinline__ void acc48(float acc[3], float v,
                                      const float* __restrict__ W, int S,
                                      int lane, int kbase) {
#pragma unroll
    for (int kk = 0; kk < 16; kk += 4) {
        float b0 = __shfl_sync(FULLM, v, kk + 0, 16);
        float b1 = __shfl_sync(FULLM, v, kk + 1, 16);
        float b2 = __shfl_sync(FULLM, v, kk + 2, 16);
        float b3 = __shfl_sync(FULLM, v, kk + 3, 16);
#pragma unroll
        for (int r = 0; r < 3; r++) {
            float4 w = *reinterpret_cast<const float4*>(
                &W[(lane + 16 * r) * S + kbase + kk]);
            acc[r] += w.x * b0 + w.y * b1 + w.z * b2 + w.w * b3;
        }
    }
}

__device__ __forceinline__ void acc16(float& acc, float v,
                                      const float* __restrict__ W, int S,
                                      int lane, int kbase) {
#pragma unroll
    for (int kk = 0; kk < 16; kk += 4) {
        float b0 = __shfl_sync(FULLM, v, kk + 0, 16);
        float b1 = __shfl_sync(FULLM, v, kk + 1, 16);
        float b2 = __shfl_sync(FULLM, v, kk + 2, 16);
        float b3 = __shfl_sync(FULLM, v, kk + 3, 16);
        float4 w = *reinterpret_cast<const float4*>(&W[lane * S + kbase + kk]);
        acc += w.x * b0 + w.y * b1 + w.z * b2 + w.w * b3;
    }
}

__device__ __forceinline__ void ln_silu3(float v[3],
                                         const float* __restrict__ g,
                                         const float* __restrict__ b,
                                         int lane) {
    float s = v[0] + v[1] + v[2];
    float q = v[0] * v[0] + v[1] * v[1] + v[2] * v[2];
#pragma unroll
    for (int off = 8; off >= 1; off >>= 1) {
        s += __shfl_xor_sync(FULLM, s, off, 16);
        q += __shfl_xor_sync(FULLM, q, off, 16);
    }
    float mu = s * (1.f / DIM1);
    float var = q * (1.f / DIM1) - mu * mu;
    float inv = rsqrtf(var + 1e-5f);
#pragma unroll
    for (int r = 0; r < 3; r++) {
        float t = (v[r] - mu) * inv * __ldg(&g[lane + 16 * r]) + __ldg(&b[lane + 16 * r]);
        v[r] = t / (1.f + expf(-t));
    }
}

__global__ void __launch_bounds__(512) rowmlp_kernel(
    const float* __restrict__ we, const float* __restrict__ ctx,
    const float* __restrict__ th,
    const float* __restrict__ WI1, const float* __restrict__ bI1,
    const float* __restrict__ WA1, const float* __restrict__ bA1,
    const float* __restrict__ WM1, const float* __restrict__ bM1,
    const float* __restrict__ WM2, const float* __restrict__ bM2,
    const float* __restrict__ WM3, const float* __restrict__ bM3,
    const float* __restrict__ lng, const float* __restrict__ lnb,
    const float* __restrict__ WO1, const float* __restrict__ bO1) {
    __shared__ __align__(16) float sWM1[DIM1 * S_M1];
    __shared__ __align__(16) float sWM2[DIM1 * S_M2];
    __shared__ __align__(16) float sWM3[DIM1 * S_M3];

    int tid = threadIdx.x;
    for (int i = tid; i < DIM1 * 80; i += 512) sWM1[(i / 80) * S_M1 + (i % 80)] = WM1[i];
    for (int i = tid; i < DIM1 * 112; i += 512) sWM2[(i / 112) * S_M2 + (i % 112)] = WM2[i];
    for (int i = tid; i < DIM1 * 48; i += 512) sWM3[(i / 48) * S_M3 + (i % 48)] = WM3[i];
    __syncthreads();

    int lane = tid & 15;
    int row = blockIdx.x * 32 + (tid >> 4);

    float x = we[(size_t)row * DIM + lane];
    float c = ctx[(size_t)row * DIM + lane];

    // layerI1: 16 -> 48
    float t0[3];
#pragma unroll
    for (int r = 0; r < 3; r++) t0[r] = __ldg(&bI1[lane + 16 * r]);
    {
#pragma unroll
        for (int kk = 0; kk < 16; kk += 4) {
            float b0 = __shfl_sync(FULLM, x, kk + 0, 16);
            float b1 = __shfl_sync(FULLM, x, kk + 1, 16);
            float b2 = __shfl_sync(FULLM, x, kk + 2, 16);
            float b3 = __shfl_sync(FULLM, x, kk + 3, 16);
#pragma unroll
            for (int r = 0; r < 3; r++) {
                float4 w = *reinterpret_cast<const float4*>(
                    &WI1[(lane + 16 * r) * 16 + kk]);
                t0[r] += w.x * b0 + w.y * b1 + w.z * b2 + w.w * b3;
            }
        }
    }

    // layerA1: 48 -> 16
    float op = __ldg(&bA1[lane]);
    acc16(op, t0[0], WA1, 48, lane, 0);
    acc16(op, t0[1], WA1, 48, lane, 16);
    acc16(op, t0[2], WA1, 48, lane, 32);

    // M1 over [t0(48), c(16), op(16)]
    float h[3];
#pragma unroll
    for (int r = 0; r < 3; r++) h[r] = __ldg(&bM1[lane + 16 * r]);
    acc48(h, t0[0], sWM1, S_M1, lane, 0);
    acc48(h, t0[1], sWM1, S_M1, lane, 16);
    acc48(h, t0[2], sWM1, S_M1, lane, 32);
    acc48(h, c, sWM1, S_M1, lane, 48);
    acc48(h, op, sWM1, S_M1, lane, 64);
    ln_silu3(h, lng, lnb, lane);

    // scores + top-3 (strict >, first occurrence == jax tie-break)
    float opAll[16];
#pragma unroll
    for (int k = 0; k < 16; k++) opAll[k] = __shfl_sync(FULLM, op, k, 16);

    const float* trow = th + (size_t)row * TTH * DIM;
    float s0 = 0.f;
    {
        const float4* tr = reinterpret_cast<const float4*>(trow + lane * DIM);
#pragma unroll
        for (int q = 0; q < 4; q++) {
            float4 a = tr[q];
            s0 += a.x * opAll[4 * q + 0] + a.y * opAll[4 * q + 1] +
                  a.z * opAll[4 * q + 2] + a.w * opAll[4 * q + 3];
        }
    }
    float s1 = -1e30f;
    if (lane < 4) {
        const float4* tr = reinterpret_cast<const float4*>(trow + (16 + lane) * DIM);
        float acc = 0.f;
#pragma unroll
        for (int q = 0; q < 4; q++) {
            float4 a = tr[q];
            acc += a.x * opAll[4 * q + 0] + a.y * opAll[4 * q + 1] +
                   a.z * opAll[4 * q + 2] + a.w * opAll[4 * q + 3];
        }
        s1 = acc;
    }
    float sc[TTH];
#pragma unroll
    for (int t = 0; t < 16; t++) sc[t] = __shfl_sync(FULLM, s0, t, 16);
#pragma unroll
    for (int t = 16; t < TTH; t++) sc[t] = __shfl_sync(FULLM, s1, t - 16, 16);

    int best[3];
#pragma unroll
    for (int s3 = 0; s3 < 3; s3++) {
        float bv = -1e30f;
        int bi = 0;
#pragma unroll
        for (int t = 0; t < TTH; t++) {
            if (sc[t] > bv) { bv = sc[t]; bi = t; }
        }
        best[s3] = bi;
#pragma unroll
        for (int t = 0; t < TTH; t++)
            if (t == bi) sc[t] = -1e30f;
    }

    float tp[3];
#pragma unroll
    for (int s3 = 0; s3 < 3; s3++) tp[s3] = __ldg(&trow[best[s3] * DIM + lane]);

    // M2 over [h(48), top_flat(48), c(16)]
    float h2[3];
#pragma unroll
    for (int r = 0; r < 3; r++) h2[r] = __ldg(&bM2[lane + 16 * r]);
    acc48(h2, h[0], sWM2, S_M2, lane, 0);
    acc48(h2, h[1], sWM2, S_M2, lane, 16);
    acc48(h2, h[2], sWM2, S_M2, lane, 32);
    acc48(h2, tp[0], sWM2, S_M2, lane, 48);
    acc48(h2, tp[1], sWM2, S_M2, lane, 64);
    acc48(h2, tp[2], sWM2, S_M2, lane, 80);
    acc48(h2, c, sWM2, S_M2, lane, 96);
    ln_silu3(h2, lng, lnb, lane);

    // M3: 48 -> 48
    float h3[3];
#pragma unroll
    for (int r = 0; r < 3; r++) h3[r] = __ldg(&bM3[lane + 16 * r]);
    acc48(h3, h2[0], sWM3, S_M3, lane, 0);
    acc48(h3, h2[1], sWM3, S_M3, lane, 16);
    acc48(h3, h2[2], sWM3, S_M3, lane, 32);
    ln_silu3(h3, lng, lnb, lane);

    // O1: 48 -> 16
    float o = __ldg(&bO1[lane]);
    acc16(o, h3[0], WO1, 48, lane, 0);
    acc16(o, h3[1], WO1, 48, lane, 16);
    acc16(o, h3[2], WO1, 48, lane, 32);

    g_o[(size_t)row * DIM + lane] = o;
}

// ---------------------------------------------------------------------------
// Kernel B: logits = o @ E^T with f32x2 pairs taken along k (natural layout,
// no duplication). Per thread: 2 vocab cols, per row 4 LDS.128 -> 16 FFMA2.
// Accumulator = {sum even k, sum odd k}; horizontal add at the end.
// ---------------------------------------------------------------------------
__device__ __forceinline__ unsigned long long ffma2(unsigned long long a,
                                                    unsigned long long b,
                                                    unsigned long long c) {
    unsigned long long d;
    asm("fma.rn.f32x2 %0, %1, %2, %3;" : "=l"(d) : "l"(a), "l"(b), "l"(c));
    return d;
}
__device__ __forceinline__ float2 unpack2(unsigned long long v) {
    float2 r;
    asm("mov.b64 {%0, %1}, %2;" : "=f"(r.x), "=f"(r.y) : "l"(v));
    return r;
}

#define BT 128  // rows per block

__global__ void __launch_bounds__(256) logits_kernel(
    const float* __restrict__ E, float* __restrict__ out) {
    // Raw o rows as natural k-pairs: 128 rows * 8 pairs = 8 KB.
    __shared__ __align__(16) unsigned long long shO[BT * 8];

    int vb = blockIdx.x * 512 + threadIdx.x * 2;
    int rb = blockIdx.y * BT;
    bool vok = vb < VOCAB;
    int vsafe = vok ? vb : 0;

    // E rows v, v+1 as natural k-pairs (contiguous loads, no packing).
    unsigned long long ew0[8], ew1[8];
    {
        const ulonglong2* e0 =
            reinterpret_cast<const ulonglong2*>(E + (size_t)vsafe * DIM);
#pragma unroll
        for (int q = 0; q < 4; q++) {
            ulonglong2 a = e0[q];      // row v,  pairs 2q, 2q+1
            ulonglong2 b = e0[q + 4];  // row v+1
            ew0[2 * q + 0] = a.x;
            ew0[2 * q + 1] = a.y;
            ew1[2 * q + 0] = b.x;
            ew1[2 * q + 1] = b.y;
        }
    }

    // Stage 128 o-rows (raw fp32, natural pairs).
    {
        const ulonglong2* src = reinterpret_cast<const ulonglong2*>(
            g_o + (size_t)rb * DIM);
        ulonglong2* dst = reinterpret_cast<ulonglong2*>(shO);
        for (int i = threadIdx.x; i < BT * 4; i += 256) dst[i] = src[i];
    }
    __syncthreads();

#pragma unroll 2
    for (int r = 0; r < BT; r++) {
        const ulonglong2* od = reinterpret_cast<const ulonglong2*>(&shO[r * 8]);
        ulonglong2 p0 = od[0];
        ulonglong2 p1 = od[1];
        ulonglong2 p2 = od[2];
        ulonglong2 p3 = od[3];
        unsigned long long a0 = 0ull, a1 = 0ull;  // two independent chains
        a0 = ffma2(ew0[0], p0.x, a0);  a1 = ffma2(ew1[0], p0.x, a1);
        a0 = ffma2(ew0[1], p0.y, a0);  a1 = ffma2(ew1[1], p0.y, a1);
        a0 = ffma2(ew0[2], p1.x, a0);  a1 = ffma2(ew1[2], p1.x, a1);
        a0 = ffma2(ew0[3], p1.y, a0);  a1 = ffma2(ew1[3], p1.y, a1);
        a0 = ffma2(ew0[4], p2.x, a0);  a1 = ffma2(ew1[4], p2.x, a1);
        a0 = ffma2(ew0[5], p2.y, a0);  a1 = ffma2(ew1[5], p2.y, a1);
        a0 = ffma2(ew0[6], p3.x, a0);  a1 = ffma2(ew1[6], p3.x, a1);
        a0 = ffma2(ew0[7], p3.y, a0);  a1 = ffma2(ew1[7], p3.y, a1);
        if (vok) {
            float2 u0 = unpack2(a0);
            float2 u1 = unpack2(a1);
            *reinterpret_cast<float2*>(out + (size_t)(rb + r) * VOCAB + vb) =
                make_float2(u0.x + u0.y, u1.x + u1.y);
        }
    }
}

// ---------------------------------------------------------------------------
extern "C" void kernel_launch(void* const* d_in, const int* in_sizes, int n_in,
                              void* d_out, int out_size) {
    const float* we  = (const float*)d_in[0];
    const float* ctx = (const float*)d_in[1];
    const float* th  = (const float*)d_in[2];
    const float* WI1 = (const float*)d_in[3];
    const float* bI1 = (const float*)d_in[4];
    const float* WA1 = (const float*)d_in[5];
    const float* bA1 = (const float*)d_in[6];
    const float* WM1 = (const float*)d_in[7];
    const float* bM1 = (const float*)d_in[8];
    const float* WM2 = (const float*)d_in[9];
    const float* bM2 = (const float*)d_in[10];
    const float* WM3 = (const float*)d_in[11];
    const float* bM3 = (const float*)d_in[12];
    const float* lng = (const float*)d_in[13];
    const float* lnb = (const float*)d_in[14];
    const float* WO1 = (const float*)d_in[15];
    const float* bO1 = (const float*)d_in[16];
    const float* E   = (const float*)d_in[17];
    float* out = (float*)d_out;

    rowmlp_kernel<<<256, 512>>>(we, ctx, th, WI1, bI1, WA1, bA1, WM1, bM1,
                                WM2, bM2, WM3, bM3, lng, lnb, WO1, bO1);
    logits_kernel<<<dim3(63, BATCH / BT), 256>>>(E, out);
}

// round 8
// speedup vs baseline: 1.8023x; 1.8023x over previous
#include <cuda_runtime.h>
#include <math.h>

#define BATCH 8192
#define DIM 16
#define DIM1 48
#define VOCAB 32000
#define TTH 20
#define FULLM 0xffffffffu

// Intermediate o = [BATCH, 16] between the two kernels (static scratch, no allocs).
__device__ float g_o[BATCH * DIM];

// ---------------------------------------------------------------------------
// Kernel A: cooperative 16-lanes-per-row MLP pipeline (unchanged WIN from R6).
// ---------------------------------------------------------------------------

#define S_M1 84   // 80 -> 84
#define S_M2 116  // 112 -> 116
#define S_M3 52   // 48 -> 52

__device__ __forceinline__ void acc48(float acc[3], float v,
                                      const float* __restrict__ W, int S,
                                      int lane, int kbase) {
#pragma unroll
    for (int kk = 0; kk < 16; kk += 4) {
        float b0 = __shfl_sync(FULLM, v, kk + 0, 16);
        float b1 = __shfl_sync(FULLM, v, kk + 1, 16);
        float b2 = __shfl_sync(FULLM, v, kk + 2, 16);
        float b3 = __shfl_sync(FULLM, v, kk + 3, 16);
#pragma unroll
        for (int r = 0; r < 3; r++) {
            float4 w = *reinterpret_cast<const float4*>(
                &W[(lane + 16 * r) * S + kbase + kk]);
            acc[r] += w.x * b0 + w.y * b1 + w.z * b2 + w.w * b3;
        }
    }
}

__device__ __forceinline__ void acc16(float& acc, float v,
                                      const float* __restrict__ W, int S,
                                      int lane, int kbase) {
#pragma unroll
    for (int kk = 0; kk < 16; kk += 4) {
        float b0 = __shfl_sync(FULLM, v, kk + 0, 16);
        float b1 = __shfl_sync(FULLM, v, kk + 1, 16);
        float b2 = __shfl_sync(FULLM, v, kk + 2, 16);
        float b3 = __shfl_sync(FULLM, v, kk + 3, 16);
        float4 w = *reinterpret_cast<const float4*>(&W[lane * S + kbase + kk]);
        acc += w.x * b0 + w.y * b1 + w.z * b2 + w.w * b3;
    }
}

__device__ __forceinline__ void ln_silu3(float v[3],
                                         const float* __restrict__ g,
                                         const float* __restrict__ b,
                                         int lane) {
    float s = v[0] + v[1] + v[2];
    float q = v[0] * v[0] + v[1] * v[1] + v[2] * v[2];
#pragma unroll
    for (int off = 8; off >= 1; off >>= 1) {
        s += __shfl_xor_sync(FULLM, s, off, 16);
        q += __shfl_xor_sync(FULLM, q, off, 16);
    }
    float mu = s * (1.f / DIM1);
    float var = q * (1.f / DIM1) - mu * mu;
    float inv = rsqrtf(var + 1e-5f);
#pragma unroll
    for (int r = 0; r < 3; r++) {
        float t = (v[r] - mu) * inv * __ldg(&g[lane + 16 * r]) + __ldg(&b[lane + 16 * r]);
        v[r] = t / (1.f + expf(-t));
    }
}

__global__ void __launch_bounds__(512) rowmlp_kernel(
    const float* __restrict__ we, const float* __restrict__ ctx,
    const float* __restrict__ th,
    const float* __restrict__ WI1, const float* __restrict__ bI1,
    const float* __restrict__ WA1, const float* __restrict__ bA1,
    const float* __restrict__ WM1, const float* __restrict__ bM1,
    const float* __restrict__ WM2, const float* __restrict__ bM2,
    const float* __restrict__ WM3, const float* __restrict__ bM3,
    const float* __restrict__ lng, const float* __restrict__ lnb,
    const float* __restrict__ WO1, const float* __restrict__ bO1) {
    __shared__ __align__(16) float sWM1[DIM1 * S_M1];
    __shared__ __align__(16) float sWM2[DIM1 * S_M2];
    __shared__ __align__(16) float sWM3[DIM1 * S_M3];

    int tid = threadIdx.x;
    for (int i = tid; i < DIM1 * 80; i += 512) sWM1[(i / 80) * S_M1 + (i % 80)] = WM1[i];
    for (int i = tid; i < DIM1 * 112; i += 512) sWM2[(i / 112) * S_M2 + (i % 112)] = WM2[i];
    for (int i = tid; i < DIM1 * 48; i += 512) sWM3[(i / 48) * S_M3 + (i % 48)] = WM3[i];
    __syncthreads();

    int lane = tid & 15;
    int row = blockIdx.x * 32 + (tid >> 4);

    float x = we[(size_t)row * DIM + lane];
    float c = ctx[(size_t)row * DIM + lane];

    // layerI1: 16 -> 48
    float t0[3];
#pragma unroll
    for (int r = 0; r < 3; r++) t0[r] = __ldg(&bI1[lane + 16 * r]);
    {
#pragma unroll
        for (int kk = 0; kk < 16; kk += 4) {
            float b0 = __shfl_sync(FULLM, x, kk + 0, 16);
            float b1 = __shfl_sync(FULLM, x, kk + 1, 16);
            float b2 = __shfl_sync(FULLM, x, kk + 2, 16);
            float b3 = __shfl_sync(FULLM, x, kk + 3, 16);
#pragma unroll
            for (int r = 0; r < 3; r++) {
                float4 w = *reinterpret_cast<const float4*>(
                    &WI1[(lane + 16 * r) * 16 + kk]);
                t0[r] += w.x * b0 + w.y * b1 + w.z * b2 + w.w * b3;
            }
        }
    }

    // layerA1: 48 -> 16
    float op = __ldg(&bA1[lane]);
    acc16(op, t0[0], WA1, 48, lane, 0);
    acc16(op, t0[1], WA1, 48, lane, 16);
    acc16(op, t0[2], WA1, 48, lane, 32);

    // M1 over [t0(48), c(16), op(16)]
    float h[3];
#pragma unroll
    for (int r = 0; r < 3; r++) h[r] = __ldg(&bM1[lane + 16 * r]);
    acc48(h, t0[0], sWM1, S_M1, lane, 0);
    acc48(h, t0[1], sWM1, S_M1, lane, 16);
    acc48(h, t0[2], sWM1, S_M1, lane, 32);
    acc48(h, c, sWM1, S_M1, lane, 48);
    acc48(h, op, sWM1, S_M1, lane, 64);
    ln_silu3(h, lng, lnb, lane);

    // scores + top-3 (strict >, first occurrence == jax tie-break)
    float opAll[16];
#pragma unroll
    for (int k = 0; k < 16; k++) opAll[k] = __shfl_sync(FULLM, op, k, 16);

    const float* trow = th + (size_t)row * TTH * DIM;
    float s0 = 0.f;
    {
        const float4* tr = reinterpret_cast<const float4*>(trow + lane * DIM);
#pragma unroll
        for (int q = 0; q < 4; q++) {
            float4 a = tr[q];
            s0 += a.x * opAll[4 * q + 0] + a.y * opAll[4 * q + 1] +
                  a.z * opAll[4 * q + 2] + a.w * opAll[4 * q + 3];
        }
    }
    float s1 = -1e30f;
    if (lane < 4) {
        const float4* tr = reinterpret_cast<const float4*>(trow + (16 + lane) * DIM);
        float acc = 0.f;
#pragma unroll
        for (int q = 0; q < 4; q++) {
            float4 a = tr[q];
            acc += a.x * opAll[4 * q + 0] + a.y * opAll[4 * q + 1] +
                   a.z * opAll[4 * q + 2] + a.w * opAll[4 * q + 3];
        }
        s1 = acc;
    }
    float sc[TTH];
#pragma unroll
    for (int t = 0; t < 16; t++) sc[t] = __shfl_sync(FULLM, s0, t, 16);
#pragma unroll
    for (int t = 16; t < TTH; t++) sc[t] = __shfl_sync(FULLM, s1, t - 16, 16);

    int best[3];
#pragma unroll
    for (int s3 = 0; s3 < 3; s3++) {
        float bv = -1e30f;
        int bi = 0;
#pragma unroll
        for (int t = 0; t < TTH; t++) {
            if (sc[t] > bv) { bv = sc[t]; bi = t; }
        }
        best[s3] = bi;
#pragma unroll
        for (int t = 0; t < TTH; t++)
            if (t == bi) sc[t] = -1e30f;
    }

    float tp[3];
#pragma unroll
    for (int s3 = 0; s3 < 3; s3++) tp[s3] = __ldg(&trow[best[s3] * DIM + lane]);

    // M2 over [h(48), top_flat(48), c(16)]
    float h2[3];
#pragma unroll
    for (int r = 0; r < 3; r++) h2[r] = __ldg(&bM2[lane + 16 * r]);
    acc48(h2, h[0], sWM2, S_M2, lane, 0);
    acc48(h2, h[1], sWM2, S_M2, lane, 16);
    acc48(h2, h[2], sWM2, S_M2, lane, 32);
    acc48(h2, tp[0], sWM2, S_M2, lane, 48);
    acc48(h2, tp[1], sWM2, S_M2, lane, 64);
    acc48(h2, tp[2], sWM2, S_M2, lane, 80);
    acc48(h2, c, sWM2, S_M2, lane, 96);
    ln_silu3(h2, lng, lnb, lane);

    // M3: 48 -> 48
    float h3[3];
#pragma unroll
    for (int r = 0; r < 3; r++) h3[r] = __ldg(&bM3[lane + 16 * r]);
    acc48(h3, h2[0], sWM3, S_M3, lane, 0);
    acc48(h3, h2[1], sWM3, S_M3, lane, 16);
    acc48(h3, h2[2], sWM3, S_M3, lane, 32);
    ln_silu3(h3, lng, lnb, lane);

    // O1: 48 -> 16
    float o = __ldg(&bO1[lane]);
    acc16(o, h3[0], WO1, 48, lane, 0);
    acc16(o, h3[1], WO1, 48, lane, 16);
    acc16(o, h3[2], WO1, 48, lane, 32);

    g_o[(size_t)row * DIM + lane] = o;
}

// ---------------------------------------------------------------------------
// Kernel B: logits = o @ E^T.
// 4 vocab cols/thread, f32x2 pairs along k for BOTH operands (natural layout):
//   per row: 4 broadcast LDS.128 (o) + 32 FFMA2 (4 indep 8-deep chains)
//            + 4 hsum + 1 STG.128.
// fma pipe is the binder; LDS ~25% of fma; hadd ~12% overhead.
// ---------------------------------------------------------------------------
__device__ __forceinline__ unsigned long long ffma2(unsigned long long a,
                                                    unsigned long long b,
                                                    unsigned long long c) {
    unsigned long long d;
    asm("fma.rn.f32x2 %0, %1, %2, %3;" : "=l"(d) : "l"(a), "l"(b), "l"(c));
    return d;
}
__device__ __forceinline__ float hsum2(unsigned long long v) {
    float lo, hi;
    asm("mov.b64 {%0, %1}, %2;" : "=f"(lo), "=f"(hi) : "l"(v));
    return lo + hi;
}

#define BT 128  // rows per block

__global__ void __launch_bounds__(256, 2) logits_kernel(
    const float* __restrict__ E, float* __restrict__ out) {
    // Raw o rows as natural k-pairs: 128 rows * 8 pairs = 8 KB.
    __shared__ __align__(16) unsigned long long shO[BT * 8];

    int vb = blockIdx.x * 1024 + threadIdx.x * 4;
    int rb = blockIdx.y * BT;
    bool vok = vb < VOCAB;  // VOCAB % 4 == 0 -> all 4 valid or none
    int vsafe = vok ? vb : 0;

    // E rows v..v+3 as natural k-pairs (contiguous 16B loads, zero packing).
    unsigned long long ew0[8], ew1[8], ew2[8], ew3[8];
    {
        const ulonglong2* e0 =
            reinterpret_cast<const ulonglong2*>(E + (size_t)vsafe * DIM);
#pragma unroll
        for (int q = 0; q < 4; q++) {
            ulonglong2 a = e0[q];       // row v
            ulonglong2 b = e0[q + 4];   // row v+1
            ulonglong2 c = e0[q + 8];   // row v+2
            ulonglong2 d = e0[q + 12];  // row v+3
            ew0[2 * q] = a.x; ew0[2 * q + 1] = a.y;
            ew1[2 * q] = b.x; ew1[2 * q + 1] = b.y;
            ew2[2 * q] = c.x; ew2[2 * q + 1] = c.y;
            ew3[2 * q] = d.x; ew3[2 * q + 1] = d.y;
        }
    }

    // Stage 128 o-rows (raw fp32, natural k-pairs).
    {
        const ulonglong2* src =
            reinterpret_cast<const ulonglong2*>(g_o + (size_t)rb * DIM);
        ulonglong2* dst = reinterpret_cast<ulonglong2*>(shO);
        for (int i = threadIdx.x; i < BT * 4; i += 256) dst[i] = src[i];
    }
    __syncthreads();

#pragma unroll 2
    for (int r = 0; r < BT; r++) {
        const ulonglong2* od = reinterpret_cast<const ulonglong2*>(&shO[r * 8]);
        ulonglong2 q0 = od[0];
        ulonglong2 q1 = od[1];
        ulonglong2 q2 = od[2];
        ulonglong2 q3 = od[3];
        unsigned long long a0 = 0ull, a1 = 0ull, a2 = 0ull, a3 = 0ull;
        // j = k-pair index 0..7; 4 independent chains (one per vocab col).
        a0 = ffma2(ew0[0], q0.x, a0); a1 = ffma2(ew1[0], q0.x, a1);
        a2 = ffma2(ew2[0], q0.x, a2); a3 = ffma2(ew3[0], q0.x, a3);
        a0 = ffma2(ew0[1], q0.y, a0); a1 = ffma2(ew1[1], q0.y, a1);
        a2 = ffma2(ew2[1], q0.y, a2); a3 = ffma2(ew3[1], q0.y, a3);
        a0 = ffma2(ew0[2], q1.x, a0); a1 = ffma2(ew1[2], q1.x, a1);
        a2 = ffma2(ew2[2], q1.x, a2); a3 = ffma2(ew3[2], q1.x, a3);
        a0 = ffma2(ew0[3], q1.y, a0); a1 = ffma2(ew1[3], q1.y, a1);
        a2 = ffma2(ew2[3], q1.y, a2); a3 = ffma2(ew3[3], q1.y, a3);
        a0 = ffma2(ew0[4], q2.x, a0); a1 = ffma2(ew1[4], q2.x, a1);
        a2 = ffma2(ew2[4], q2.x, a2); a3 = ffma2(ew3[4], q2.x, a3);
        a0 = ffma2(ew0[5], q2.y, a0); a1 = ffma2(ew1[5], q2.y, a1);
        a2 = ffma2(ew2[5], q2.y, a2); a3 = ffma2(ew3[5], q2.y, a3);
        a0 = ffma2(ew0[6], q3.x, a0); a1 = ffma2(ew1[6], q3.x, a1);
        a2 = ffma2(ew2[6], q3.x, a2); a3 = ffma2(ew3[6], q3.x, a3);
        a0 = ffma2(ew0[7], q3.y, a0); a1 = ffma2(ew1[7], q3.y, a1);
        a2 = ffma2(ew2[7], q3.y, a2); a3 = ffma2(ew3[7], q3.y, a3);
        if (vok) {
            float4 res = make_float4(hsum2(a0), hsum2(a1), hsum2(a2), hsum2(a3));
            *reinterpret_cast<float4*>(out + (size_t)(rb + r) * VOCAB + vb) = res;
        }
    }
}

// ---------------------------------------------------------------------------
extern "C" void kernel_launch(void* const* d_in, const int* in_sizes, int n_in,
                              void* d_out, int out_size) {
    const float* we  = (const float*)d_in[0];
    const float* ctx = (const float*)d_in[1];
    const float* th  = (const float*)d_in[2];
    const float* WI1 = (const float*)d_in[3];
    const float* bI1 = (const float*)d_in[4];
    const float* WA1 = (const float*)d_in[5];
    const float* bA1 = (const float*)d_in[6];
    const float* WM1 = (const float*)d_in[7];
    const float* bM1 = (const float*)d_in[8];
    const float* WM2 = (const float*)d_in[9];
    const float* bM2 = (const float*)d_in[10];
    const float* WM3 = (const float*)d_in[11];
    const float* bM3 = (const float*)d_in[12];
    const float* lng = (const float*)d_in[13];
    const float* lnb = (const float*)d_in[14];
    const float* WO1 = (const float*)d_in[15];
    const float* bO1 = (const float*)d_in[16];
    const float* E   = (const float*)d_in[17];
    float* out = (float*)d_out;

    rowmlp_kernel<<<256, 512>>>(we, ctx, th, WI1, bI1, WA1, bA1, WM1, bM1,
                                WM2, bM2, WM3, bM3, lng, lnb, WO1, bO1);
    // 1024 cols/block -> 32 x-blocks (last partial); 64 y-blocks.
    logits_kernel<<<dim3(32, BATCH / BT), 256>>>(E, out);
}

// round 13
// speedup vs baseline: 1.8381x; 1.0199x over previous
#include <cuda_runtime.h>
#include <math.h>

#define BATCH 8192
#define DIM 16
#define DIM1 48
#define VOCAB 32000
#define TTH 20
#define FULLM 0xffffffffu

// Intermediate o = [BATCH, 16] between the two kernels (static scratch, no allocs).
__device__ float g_o[BATCH * DIM];

// ---------------------------------------------------------------------------
// Kernel A: cooperative 16-lanes-per-row MLP pipeline (unchanged WIN from R6).
// ---------------------------------------------------------------------------

#define S_M1 84   // 80 -> 84
#define S_M2 116  // 112 -> 116
#define S_M3 52   // 48 -> 52

__device__ __forceinline__ void acc48(float acc[3], float v,
                                      const float* __restrict__ W, int S,
                                      int lane, int kbase) {
#pragma unroll
    for (int kk = 0; kk < 16; kk += 4) {
        float b0 = __shfl_sync(FULLM, v, kk + 0, 16);
        float b1 = __shfl_sync(FULLM, v, kk + 1, 16);
        float b2 = __shfl_sync(FULLM, v, kk + 2, 16);
        float b3 = __shfl_sync(FULLM, v, kk + 3, 16);
#pragma unroll
        for (int r = 0; r < 3; r++) {
            float4 w = *reinterpret_cast<const float4*>(
                &W[(lane + 16 * r) * S + kbase + kk]);
            acc[r] += w.x * b0 + w.y * b1 + w.z * b2 + w.w * b3;
        }
    }
}

__device__ __forceinline__ void acc16(float& acc, float v,
                                      const float* __restrict__ W, int S,
                                      int lane, int kbase) {
#pragma unroll
    for (int kk = 0; kk < 16; kk += 4) {
        float b0 = __shfl_sync(FULLM, v, kk + 0, 16);
        float b1 = __shfl_sync(FULLM, v, kk + 1, 16);
        float b2 = __shfl_sync(FULLM, v, kk + 2, 16);
        float b3 = __shfl_sync(FULLM, v, kk + 3, 16);
        float4 w = *reinterpret_cast<const float4*>(&W[lane * S + kbase + kk]);
        acc += w.x * b0 + w.y * b1 + w.z * b2 + w.w * b3;
    }
}

__device__ __forceinline__ void ln_silu3(float v[3],
                                         const float* __restrict__ g,
                                         const float* __restrict__ b,
                                         int lane) {
    float s = v[0] + v[1] + v[2];
    float q = v[0] * v[0] + v[1] * v[1] + v[2] * v[2];
#pragma unroll
    for (int off = 8; off >= 1; off >>= 1) {
        s += __shfl_xor_sync(FULLM, s, off, 16);
        q += __shfl_xor_sync(FULLM, q, off, 16);
    }
    float mu = s * (1.f / DIM1);
    float var = q * (1.f / DIM1) - mu * mu;
    float inv = rsqrtf(var + 1e-5f);
#pragma unroll
    for (int r = 0; r < 3; r++) {
        float t = (v[r] - mu) * inv * __ldg(&g[lane + 16 * r]) + __ldg(&b[lane + 16 * r]);
        v[r] = t / (1.f + expf(-t));
    }
}

__global__ void __launch_bounds__(512) rowmlp_kernel(
    const float* __restrict__ we, const float* __restrict__ ctx,
    const float* __restrict__ th,
    const float* __restrict__ WI1, const float* __restrict__ bI1,
    const float* __restrict__ WA1, const float* __restrict__ bA1,
    const float* __restrict__ WM1, const float* __restrict__ bM1,
    const float* __restrict__ WM2, const float* __restrict__ bM2,
    const float* __restrict__ WM3, const float* __restrict__ bM3,
    const float* __restrict__ lng, const float* __restrict__ lnb,
    const float* __restrict__ WO1, const float* __restrict__ bO1) {
    __shared__ __align__(16) float sWM1[DIM1 * S_M1];
    __shared__ __align__(16) float sWM2[DIM1 * S_M2];
    __shared__ __align__(16) float sWM3[DIM1 * S_M3];

    int tid = threadIdx.x;
    for (int i = tid; i < DIM1 * 80; i += 512) sWM1[(i / 80) * S_M1 + (i % 80)] = WM1[i];
    for (int i = tid; i < DIM1 * 112; i += 512) sWM2[(i / 112) * S_M2 + (i % 112)] = WM2[i];
    for (int i = tid; i < DIM1 * 48; i += 512) sWM3[(i / 48) * S_M3 + (i % 48)] = WM3[i];
    __syncthreads();

    int lane = tid & 15;
    int row = blockIdx.x * 32 + (tid >> 4);

    float x = we[(size_t)row * DIM + lane];
    float c = ctx[(size_t)row * DIM + lane];

    // layerI1: 16 -> 48
    float t0[3];
#pragma unroll
    for (int r = 0; r < 3; r++) t0[r] = __ldg(&bI1[lane + 16 * r]);
    {
#pragma unroll
        for (int kk = 0; kk < 16; kk += 4) {
            float b0 = __shfl_sync(FULLM, x, kk + 0, 16);
            float b1 = __shfl_sync(FULLM, x, kk + 1, 16);
            float b2 = __shfl_sync(FULLM, x, kk + 2, 16);
            float b3 = __shfl_sync(FULLM, x, kk + 3, 16);
#pragma unroll
            for (int r = 0; r < 3; r++) {
                float4 w = *reinterpret_cast<const float4*>(
                    &WI1[(lane + 16 * r) * 16 + kk]);
                t0[r] += w.x * b0 + w.y * b1 + w.z * b2 + w.w * b3;
            }
        }
    }

    // layerA1: 48 -> 16
    float op = __ldg(&bA1[lane]);
    acc16(op, t0[0], WA1, 48, lane, 0);
    acc16(op, t0[1], WA1, 48, lane, 16);
    acc16(op, t0[2], WA1, 48, lane, 32);

    // M1 over [t0(48), c(16), op(16)]
    float h[3];
#pragma unroll
    for (int r = 0; r < 3; r++) h[r] = __ldg(&bM1[lane + 16 * r]);
    acc48(h, t0[0], sWM1, S_M1, lane, 0);
    acc48(h, t0[1], sWM1, S_M1, lane, 16);
    acc48(h, t0[2], sWM1, S_M1, lane, 32);
    acc48(h, c, sWM1, S_M1, lane, 48);
    acc48(h, op, sWM1, S_M1, lane, 64);
    ln_silu3(h, lng, lnb, lane);

    // scores + top-3 (strict >, first occurrence == jax tie-break)
    float opAll[16];
#pragma unroll
    for (int k = 0; k < 16; k++) opAll[k] = __shfl_sync(FULLM, op, k, 16);

    const float* trow = th + (size_t)row * TTH * DIM;
    float s0 = 0.f;
    {
        const float4* tr = reinterpret_cast<const float4*>(trow + lane * DIM);
#pragma unroll
        for (int q = 0; q < 4; q++) {
            float4 a = tr[q];
            s0 += a.x * opAll[4 * q + 0] + a.y * opAll[4 * q + 1] +
                  a.z * opAll[4 * q + 2] + a.w * opAll[4 * q + 3];
        }
    }
    float s1 = -1e30f;
    if (lane < 4) {
        const float4* tr = reinterpret_cast<const float4*>(trow + (16 + lane) * DIM);
        float acc = 0.f;
#pragma unroll
        for (int q = 0; q < 4; q++) {
            float4 a = tr[q];
            acc += a.x * opAll[4 * q + 0] + a.y * opAll[4 * q + 1] +
                   a.z * opAll[4 * q + 2] + a.w * opAll[4 * q + 3];
        }
        s1 = acc;
    }
    float sc[TTH];
#pragma unroll
    for (int t = 0; t < 16; t++) sc[t] = __shfl_sync(FULLM, s0, t, 16);
#pragma unroll
    for (int t = 16; t < TTH; t++) sc[t] = __shfl_sync(FULLM, s1, t - 16, 16);

    int best[3];
#pragma unroll
    for (int s3 = 0; s3 < 3; s3++) {
        float bv = -1e30f;
        int bi = 0;
#pragma unroll
        for (int t = 0; t < TTH; t++) {
            if (sc[t] > bv) { bv = sc[t]; bi = t; }
        }
        best[s3] = bi;
#pragma unroll
        for (int t = 0; t < TTH; t++)
            if (t == bi) sc[t] = -1e30f;
    }

    float tp[3];
#pragma unroll
    for (int s3 = 0; s3 < 3; s3++) tp[s3] = __ldg(&trow[best[s3] * DIM + lane]);

    // M2 over [h(48), top_flat(48), c(16)]
    float h2[3];
#pragma unroll
    for (int r = 0; r < 3; r++) h2[r] = __ldg(&bM2[lane + 16 * r]);
    acc48(h2, h[0], sWM2, S_M2, lane, 0);
    acc48(h2, h[1], sWM2, S_M2, lane, 16);
    acc48(h2, h[2], sWM2, S_M2, lane, 32);
    acc48(h2, tp[0], sWM2, S_M2, lane, 48);
    acc48(h2, tp[1], sWM2, S_M2, lane, 64);
    acc48(h2, tp[2], sWM2, S_M2, lane, 80);
    acc48(h2, c, sWM2, S_M2, lane, 96);
    ln_silu3(h2, lng, lnb, lane);

    // M3: 48 -> 48
    float h3[3];
#pragma unroll
    for (int r = 0; r < 3; r++) h3[r] = __ldg(&bM3[lane + 16 * r]);
    acc48(h3, h2[0], sWM3, S_M3, lane, 0);
    acc48(h3, h2[1], sWM3, S_M3, lane, 16);
    acc48(h3, h2[2], sWM3, S_M3, lane, 32);
    ln_silu3(h3, lng, lnb, lane);

    // O1: 48 -> 16
    float o = __ldg(&bO1[lane]);
    acc16(o, h3[0], WO1, 48, lane, 0);
    acc16(o, h3[1], WO1, 48, lane, 16);
    acc16(o, h3[2], WO1, 48, lane, 32);

    g_o[(size_t)row * DIM + lane] = o;
}

// ---------------------------------------------------------------------------
// Kernel B: logits = o @ E^T.
// Same k-paired FFMA2 algorithm as R8 (fma-busy ~= floor), but 128-thread
// blocks: reg granularity gives ~5 blocks/SM -> 20 warps/SM (was 12) to
// overlap LDS latency + STG drain with the fma stream. Streaming stores
// (st.global.cs) keep the 1 GB write-once output from thrashing E in L2.
// ---------------------------------------------------------------------------
__device__ __forceinline__ unsigned long long ffma2(unsigned long long a,
                                                    unsigned long long b,
                                                    unsigned long long c) {
    unsigned long long d;
    asm("fma.rn.f32x2 %0, %1, %2, %3;" : "=l"(d) : "l"(a), "l"(b), "l"(c));
    return d;
}
__device__ __forceinline__ float hsum2(unsigned long long v) {
    float lo, hi;
    asm("mov.b64 {%0, %1}, %2;" : "=f"(lo), "=f"(hi) : "l"(v));
    return lo + hi;
}

#define BT 128  // rows per block

__global__ void __launch_bounds__(128, 5) logits_kernel(
    const float* __restrict__ E, float* __restrict__ out) {
    // Raw o rows as natural k-pairs: 128 rows * 8 pairs = 8 KB.
    __shared__ __align__(16) unsigned long long shO[BT * 8];

    int vb = blockIdx.x * 512 + threadIdx.x * 4;
    int rb = blockIdx.y * BT;
    bool vok = vb < VOCAB;  // VOCAB % 4 == 0 -> all 4 valid or none
    int vsafe = vok ? vb : 0;

    // E rows v..v+3 as natural k-pairs (contiguous 16B loads, zero packing).
    unsigned long long ew0[8], ew1[8], ew2[8], ew3[8];
    {
        const ulonglong2* e0 =
            reinterpret_cast<const ulonglong2*>(E + (size_t)vsafe * DIM);
#pragma unroll
        for (int q = 0; q < 4; q++) {
            ulonglong2 a = e0[q];       // row v
            ulonglong2 b = e0[q + 4];   // row v+1
            ulonglong2 c = e0[q + 8];   // row v+2
            ulonglong2 d = e0[q + 12];  // row v+3
            ew0[2 * q] = a.x; ew0[2 * q + 1] = a.y;
            ew1[2 * q] = b.x; ew1[2 * q + 1] = b.y;
            ew2[2 * q] = c.x; ew2[2 * q + 1] = c.y;
            ew3[2 * q] = d.x; ew3[2 * q + 1] = d.y;
        }
    }

    // Stage 128 o-rows (raw fp32, natural k-pairs).
    {
        const ulonglong2* src =
            reinterpret_cast<const ulonglong2*>(g_o + (size_t)rb * DIM);
        ulonglong2* dst = reinterpret_cast<ulonglong2*>(shO);
        for (int i = threadIdx.x; i < BT * 4; i += 128) dst[i] = src[i];
    }
    __syncthreads();

#pragma unroll 2
    for (int r = 0; r < BT; r++) {
        const ulonglong2* od = reinterpret_cast<const ulonglong2*>(&shO[r * 8]);
        ulonglong2 q0 = od[0];
        ulonglong2 q1 = od[1];
        ulonglong2 q2 = od[2];
        ulonglong2 q3 = od[3];
        unsigned long long a0 = 0ull, a1 = 0ull, a2 = 0ull, a3 = 0ull;
        // k-pair index 0..7; 4 independent chains (one per vocab col).
        a0 = ffma2(ew0[0], q0.x, a0); a1 = ffma2(ew1[0], q0.x, a1);
        a2 = ffma2(ew2[0], q0.x, a2); a3 = ffma2(ew3[0], q0.x, a3);
        a0 = ffma2(ew0[1], q0.y, a0); a1 = ffma2(ew1[1], q0.y, a1);
        a2 = ffma2(ew2[1], q0.y, a2); a3 = ffma2(ew3[1], q0.y, a3);
        a0 = ffma2(ew0[2], q1.x, a0); a1 = ffma2(ew1[2], q1.x, a1);
        a2 = ffma2(ew2[2], q1.x, a2); a3 = ffma2(ew3[2], q1.x, a3);
        a0 = ffma2(ew0[3], q1.y, a0); a1 = ffma2(ew1[3], q1.y, a1);
        a2 = ffma2(ew2[3], q1.y, a2); a3 = ffma2(ew3[3], q1.y, a3);
        a0 = ffma2(ew0[4], q2.x, a0); a1 = ffma2(ew1[4], q2.x, a1);
        a2 = ffma2(ew2[4], q2.x, a2); a3 = ffma2(ew3[4], q2.x, a3);
        a0 = ffma2(ew0[5], q2.y, a0); a1 = ffma2(ew1[5], q2.y, a1);
        a2 = ffma2(ew2[5], q2.y, a2); a3 = ffma2(ew3[5], q2.y, a3);
        a0 = ffma2(ew0[6], q3.x, a0); a1 = ffma2(ew1[6], q3.x, a1);
        a2 = ffma2(ew2[6], q3.x, a2); a3 = ffma2(ew3[6], q3.x, a3);
        a0 = ffma2(ew0[7], q3.y, a0); a1 = ffma2(ew1[7], q3.y, a1);
        a2 = ffma2(ew2[7], q3.y, a2); a3 = ffma2(ew3[7], q3.y, a3);
        if (vok) {
            float4 res = make_float4(hsum2(a0), hsum2(a1), hsum2(a2), hsum2(a3));
            __stcs(reinterpret_cast<float4*>(out + (size_t)(rb + r) * VOCAB + vb),
                   res);
        }
    }
}

// ---------------------------------------------------------------------------
extern "C" void kernel_launch(void* const* d_in, const int* in_sizes, int n_in,
                              void* d_out, int out_size) {
    const float* we  = (const float*)d_in[0];
    const float* ctx = (const float*)d_in[1];
    const float* th  = (const float*)d_in[2];
    const float* WI1 = (const float*)d_in[3];
    const float* bI1 = (const float*)d_in[4];
    const float* WA1 = (const float*)d_in[5];
    const float* bA1 = (const float*)d_in[6];
    const float* WM1 = (const float*)d_in[7];
    const float* bM1 = (const float*)d_in[8];
    const float* WM2 = (const float*)d_in[9];
    const float* bM2 = (const float*)d_in[10];
    const float* WM3 = (const float*)d_in[11];
    const float* bM3 = (const float*)d_in[12];
    const float* lng = (const float*)d_in[13];
    const float* lnb = (const float*)d_in[14];
    const float* WO1 = (const float*)d_in[15];
    const float* bO1 = (const float*)d_in[16];
    const float* E   = (const float*)d_in[17];
    float* out = (float*)d_out;

    rowmlp_kernel<<<256, 512>>>(we, ctx, th, WI1, bI1, WA1, bA1, WM1, bM1,
                                WM2, bM2, WM3, bM3, lng, lnb, WO1, bO1);
    // 512 cols/block -> 63 x-blocks; 64 y-blocks.
    logits_kernel<<<dim3(63, BATCH / BT), 128>>>(E, out);
}